// round 7
// baseline (speedup 1.0000x reference)
#include <cuda_runtime.h>

// Problem constants (fixed by setup_inputs: img [1,1,544,960], T=8, R=4)
#define H  544
#define W  960
#define T  8
#define R  4
#define HB (H/T)                  // 68
#define WB (W/T)                  // 120
#define NB (HB*WB)                // 8160
#define NC ((2*R+1)*(2*R+1))      // 81
#define WIN (T + 2*R)             // 16
#define GRID 1020                 // CTAs; 7/SM x 148 SMs = 1036 >= 1020 (all resident)

// ---------------- scratch (device globals) ----------------------------------
__device__ float         g_cur_blur[H*W];
__device__ unsigned char g_cur_q[H*W];
__device__ unsigned char g_prev_q[H*W];
__device__ char2         g_vec[NB];          // (vy, vx) = (-dy, -dx)
__device__ unsigned      g_barrier[2];        // zero-initialized at module load

// spiral rank LUT (row-major over (dy+R, dx+R)), precomputed for R=4
__constant__ unsigned char c_spiral[NC] = {
    74, 73, 72, 71, 70, 69, 68, 67, 66,
    75, 44, 43, 42, 41, 40, 39, 38, 65,
    76, 45, 22, 21, 20, 19, 18, 37, 64,
    77, 46, 23,  8,  7,  6, 17, 36, 63,
    78, 47, 24,  9,  1,  5, 16, 35, 62,
    79, 48, 25,  2,  3,  4, 15, 34, 61,
    80, 49, 10, 11, 12, 13, 14, 33, 60,
    81, 26, 27, 28, 29, 30, 31, 32, 59,
    50, 51, 52, 53, 54, 55, 56, 57, 58
};

__device__ __forceinline__ unsigned char quant8(float v) {
    return (unsigned char)fminf(fmaxf(rintf(v * 255.0f), 0.0f), 255.0f);
}
__device__ __forceinline__ int clampi(int v, int lo, int hi) {
    return min(max(v, lo), hi);
}

// Replay-safe grid barrier: monotonic ticket counter, never reset.
// All GRID CTAs are guaranteed resident (launch bounds), so spinning is safe.
__device__ __forceinline__ void grid_barrier(unsigned* ctr) {
    __syncthreads();
    if (threadIdx.x == 0) {
        __threadfence();                              // publish our stores
        unsigned t = atomicAdd(ctr, 1u);
        unsigned target = t - (t % GRID) + GRID;      // end of this barrier epoch
        while (*(volatile unsigned*)ctr < target) { } // L2 spin (~234cyc/read backoff)
        __threadfence();                              // acquire others' stores
    }
    __syncthreads();
}

// ---------------- packed byte-SIMD median of 9 (Paeth network) --------------
#define SWU(a,b) { unsigned _t = __vminu4(a,b); b = __vmaxu4(a,b); a = _t; }
__device__ __forceinline__ unsigned med9u(unsigned v0, unsigned v1, unsigned v2,
                                          unsigned v3, unsigned v4, unsigned v5,
                                          unsigned v6, unsigned v7, unsigned v8) {
    SWU(v1,v2) SWU(v4,v5) SWU(v7,v8)
    SWU(v0,v1) SWU(v3,v4) SWU(v6,v7)
    SWU(v1,v2) SWU(v4,v5) SWU(v7,v8)
    SWU(v0,v3) SWU(v5,v8) SWU(v4,v7)
    SWU(v3,v6) SWU(v1,v4) SWU(v2,v5)
    SWU(v4,v7) SWU(v4,v2) SWU(v6,v4)
    SWU(v4,v2)
    return v4;
}

// ================= single persistent kernel: blur -> match -> flow ===========
__global__ void __launch_bounds__(256, 7) mono_kernel(const float* __restrict__ cur,
                                                      const float* __restrict__ prev,
                                                      float* __restrict__ out) {
    __shared__ unsigned win[8][WIN][5];   // per-warp 16x16 window (+pad word)
    __shared__ unsigned tmplw[8][T][2];   // per-warp 8x8 template

    const int tid  = threadIdx.x;
    const int b    = blockIdx.x;          // 0..1019
    const int wid  = tid >> 5;
    const int lane = tid & 31;

    // ======================= Phase A: binomial blur + quantize ==============
    // CTA b handles a 64x8 pixel tile: (b%15)*64 x-range, (b/15)*8 y-range.
    // Warp = one row of 64 px, 2 px/lane (proven R3 geometry: 6.4us standalone).
    {
        const int gx = b % 15, gy = b / 15;
        const int x2 = (gx * 32 + lane) * 2;
        const int y  = gy * 8 + wid;
        const int yu = max(y - 1, 0) * W;
        const int ym = y * W;
        const int yd = min(y + 1, H - 1) * W;
        const int xl = max(x2 - 1, 0);
        const int xr = min(x2 + 2, W - 1);

#pragma unroll
        for (int im = 0; im < 2; im++) {
            const float* __restrict__ img = im ? prev : cur;
            float2 u = *(const float2*)&img[yu + x2];
            float2 m = *(const float2*)&img[ym + x2];
            float2 d = *(const float2*)&img[yd + x2];
            float v0 = (u.x + 2.0f * m.x + d.x) * 0.25f;
            float v1 = (u.y + 2.0f * m.y + d.y) * 0.25f;
            float vL = __shfl_up_sync(0xffffffffu, v1, 1);
            float vR = __shfl_down_sync(0xffffffffu, v0, 1);
            if (lane == 0)
                vL = (img[yu + xl] + 2.0f * img[ym + xl] + img[yd + xl]) * 0.25f;
            if (lane == 31)
                vR = (img[yu + xr] + 2.0f * img[ym + xr] + img[yd + xr]) * 0.25f;
            float o0 = (vL + 2.0f * v0 + v1) * 0.25f;
            float o1 = (v0 + 2.0f * v1 + vR) * 0.25f;
            if (im == 0) {
                *(float2*)&g_cur_blur[ym + x2] = make_float2(o0, o1);
                *(uchar2*)&g_cur_q[ym + x2]    = make_uchar2(quant8(o0), quant8(o1));
            } else {
                *(uchar2*)&g_prev_q[ym + x2]   = make_uchar2(quant8(o0), quant8(o1));
            }
        }
    }

    grid_barrier(&g_barrier[0]);

    // ======================= Phase B: SAD match (warp per block) ============
    {
        const int blk = b * 8 + wid;
        const int by = blk / WB, bx = blk % WB;

        // 16x16 search window of prev_q (2 rows of 8B per lane)
        {
            const int wy  = lane >> 1;
            const int wx0 = (lane & 1) * 8;
            const bool interior = (by >= 1 && by <= HB - 2 && bx >= 1 && bx <= WB - 2);
            unsigned lo, hi;
            if (interior) {
                const unsigned char* p = g_prev_q + (by * T - R + wy) * W + bx * T - R + wx0;
                lo = *(const unsigned*)p;
                hi = *(const unsigned*)(p + 4);
            } else {
                lo = 0; hi = 0;
                int gy = clampi(by * T - R + wy, 0, H - 1);
#pragma unroll
                for (int c = 0; c < 4; c++) {
                    int gx = clampi(bx * T - R + wx0 + c, 0, W - 1);
                    lo |= (unsigned)g_prev_q[gy * W + gx] << (8 * c);
                }
#pragma unroll
                for (int c = 0; c < 4; c++) {
                    int gx = clampi(bx * T - R + wx0 + 4 + c, 0, W - 1);
                    hi |= (unsigned)g_prev_q[gy * W + gx] << (8 * c);
                }
            }
            win[wid][wy][wx0 >> 2]       = lo;
            win[wid][wy][(wx0 >> 2) + 1] = hi;
        }
        // template rows -> smem (lanes 0..7, one row each)
        if (lane < T) {
            uint2 t = *(const uint2*)(g_cur_q + (by * T + lane) * W + bx * T);
            tmplw[wid][lane][0] = t.x;
            tmplw[wid][lane][1] = t.y;
        }
        __syncwarp();

        unsigned key = 0xffffffffu;
#pragma unroll
        for (int j = 0; j < 3; j++) {
            int c = lane + j * 32;
            if (c < NC) {
                int cy = c / 9, cx = c - cy * 9;
                int k8 = (cx & 3) * 8, bw = cx >> 2;
                unsigned sad = 0;
#pragma unroll
                for (int ty = 0; ty < T; ty++) {
                    const unsigned* row = &win[wid][ty + cy][0];
                    unsigned w0 = row[bw], w1 = row[bw + 1], w2 = row[bw + 2];
                    unsigned lo = __funnelshift_r(w0, w1, k8);
                    unsigned hi = __funnelshift_r(w1, w2, k8);
                    sad += __vsadu4(lo, tmplw[wid][ty][0]) + __vsadu4(hi, tmplw[wid][ty][1]);
                }
                unsigned kk = ((sad * 128u + (unsigned)c_spiral[c]) << 7) | (unsigned)c;
                key = min(key, kk);
            }
        }
#pragma unroll
        for (int s = 16; s > 0; s >>= 1)
            key = min(key, __shfl_xor_sync(0xffffffffu, key, s));

        if (lane == 0) {
            int c  = key & 127;
            int dy = c / 9 - R;
            int dx = c % 9 - R;
            g_vec[blk] = make_char2((char)(-dy), (char)(-dx));
        }
    }

    grid_barrier(&g_barrier[1]);

    // ======================= Phase C: median + LK subpixel + output =========
    {
        const int blk = b * 8 + wid;
        const int by = blk / WB, bx = blk % WB;

        // lanes 0..8 load 3x3 vec neighborhood; pack (vy+4) | (vx+4)<<8
        unsigned pk = 0;
        if (lane < 9) {
            int ny = clampi(by + lane / 3 - 1, 0, HB - 1);
            int nx = clampi(bx + lane % 3 - 1, 0, WB - 1);
            char2 v = g_vec[ny * WB + nx];
            pk = (unsigned)(v.x + 4) | ((unsigned)(v.y + 4) << 8);
        }
        unsigned a0 = __shfl_sync(0xffffffffu, pk, 0);
        unsigned a1 = __shfl_sync(0xffffffffu, pk, 1);
        unsigned a2 = __shfl_sync(0xffffffffu, pk, 2);
        unsigned a3 = __shfl_sync(0xffffffffu, pk, 3);
        unsigned a4 = __shfl_sync(0xffffffffu, pk, 4);
        unsigned a5 = __shfl_sync(0xffffffffu, pk, 5);
        unsigned a6 = __shfl_sync(0xffffffffu, pk, 6);
        unsigned a7 = __shfl_sync(0xffffffffu, pk, 7);
        unsigned a8 = __shfl_sync(0xffffffffu, pk, 8);
        unsigned md = med9u(a0,a1,a2,a3,a4,a5,a6,a7,a8);
        int medy = (int)(md & 0xff) - 4;
        int medx = (int)((md >> 8) & 0xff) - 4;
        int offy = -medy, offx = -medx;

        // lane -> border pixel (28 border pixels of the 8x8 block)
        int ty, tx;
        bool act = lane < 28;
        if      (lane < 8)  { ty = 0;         tx = lane;      }
        else if (lane < 16) { ty = 7;         tx = lane - 8;  }
        else if (lane < 22) { ty = lane - 15; tx = 0;         }
        else                { ty = lane - 21; tx = 7;         }

        float a = 0.f, bb = 0.f, d = 0.f, p = 0.f, q = 0.f;
        if (act) {
            int gy0 = by * T + ty, gx0 = bx * T + tx;
            float gyv = (g_cur_blur[min(gy0 + 1, H - 1) * W + gx0] -
                         g_cur_blur[max(gy0 - 1, 0)     * W + gx0]) * 0.5f;
            float gxv = (g_cur_blur[gy0 * W + min(gx0 + 1, W - 1)] -
                         g_cur_blur[gy0 * W + max(gx0 - 1, 0)]) * 0.5f;
            float tmpl = (float)g_cur_q[gy0 * W + gx0] * (1.0f / 255.0f);
            int my = clampi(gy0 + offy, 0, H - 1);
            int mx = clampi(gx0 + offx, 0, W - 1);
            float mat  = (float)g_prev_q[my * W + mx] * (1.0f / 255.0f);
            float diff = mat - tmpl;
            a  = gxv * gxv;
            bb = gxv * gyv;
            d  = gyv * gyv;
            p  = diff * gxv;
            q  = diff * gyv;
        }
#pragma unroll
        for (int s = 16; s > 0; s >>= 1) {
            a  += __shfl_xor_sync(0xffffffffu, a,  s);
            bb += __shfl_xor_sync(0xffffffffu, bb, s);
            d  += __shfl_xor_sync(0xffffffffu, d,  s);
            p  += __shfl_xor_sync(0xffffffffu, p,  s);
            q  += __shfl_xor_sync(0xffffffffu, q,  s);
        }
        if (lane == 0) {
            float det = a * d - bb * bb;
            bool  bad = (det <= 1e-6f);
            float sd  = bad ? 1.0f : det;
            float su  = (d * p - bb * q) / sd;
            float sv  = (a * q - bb * p) / sd;
            float subv = (bad || fabsf(sv) >= 1.0f) ? 0.0f : sv;
            float subu = (bad || fabsf(su) >= 1.0f) ? 0.0f : su;
            out[blk]      = (float)medy + subv;
            out[NB + blk] = (float)medx + subu;
        }
    }
}

// ---------------- entry point ------------------------------------------------
extern "C" void kernel_launch(void* const* d_in, const int* in_sizes, int n_in,
                              void* d_out, int out_size) {
    const float* cur  = (const float*)d_in[0];
    const float* prev = (const float*)d_in[1];
    float* out = (float*)d_out;
    mono_kernel<<<GRID, 256>>>(cur, prev, out);
}

// round 8
// speedup vs baseline: 1.0078x; 1.0078x over previous
#include <cuda_runtime.h>

// Problem constants (fixed by setup_inputs: img [1,1,544,960], T=8, R=4)
#define H  544
#define W  960
#define T  8
#define R  4
#define HB (H/T)                  // 68
#define WB (W/T)                  // 120
#define NB (HB*WB)                // 8160
#define NC ((2*R+1)*(2*R+1))      // 81
#define GRID 1020                 // 7/SM x 148 SMs = 1036 >= 1020 (all resident)

// ---------------- scratch (device globals) ----------------------------------
__device__ float         g_cur_blur[H*W];
__device__ unsigned char g_cur_q[H*W];
__device__ unsigned char g_prev_q[H*W];
__device__ char2         g_vec[NB];          // (vy, vx) = (-dy, -dx)
__device__ unsigned      g_barrier;          // monotonic ticket counter

// spiral rank LUT (row-major over (dy+R, dx+R)), precomputed for R=4
__constant__ unsigned char c_spiral[NC] = {
    74, 73, 72, 71, 70, 69, 68, 67, 66,
    75, 44, 43, 42, 41, 40, 39, 38, 65,
    76, 45, 22, 21, 20, 19, 18, 37, 64,
    77, 46, 23,  8,  7,  6, 17, 36, 63,
    78, 47, 24,  9,  1,  5, 16, 35, 62,
    79, 48, 25,  2,  3,  4, 15, 34, 61,
    80, 49, 10, 11, 12, 13, 14, 33, 60,
    81, 26, 27, 28, 29, 30, 31, 32, 59,
    50, 51, 52, 53, 54, 55, 56, 57, 58
};

__device__ __forceinline__ unsigned char quant8(float v) {
    return (unsigned char)fminf(fmaxf(rintf(v * 255.0f), 0.0f), 255.0f);
}
__device__ __forceinline__ int clampi(int v, int lo, int hi) {
    return min(max(v, lo), hi);
}

// Replay-safe grid barrier: monotonic ticket counter (never reset) with
// nanosleep backoff to avoid hammering one L2 line from 1020 spinners.
__device__ __forceinline__ void grid_barrier(unsigned* ctr) {
    __syncthreads();
    if (threadIdx.x == 0) {
        __threadfence();
        unsigned t = atomicAdd(ctr, 1u);
        unsigned target = t - (t % GRID) + GRID;
        while (*(volatile unsigned*)ctr < target) __nanosleep(64);
        __threadfence();
    }
    __syncthreads();
}

// ---------------- packed byte-SIMD median of 9 (Paeth network) --------------
#define SWU(a,b) { unsigned _t = __vminu4(a,b); b = __vmaxu4(a,b); a = _t; }
__device__ __forceinline__ unsigned med9u(unsigned v0, unsigned v1, unsigned v2,
                                          unsigned v3, unsigned v4, unsigned v5,
                                          unsigned v6, unsigned v7, unsigned v8) {
    SWU(v1,v2) SWU(v4,v5) SWU(v7,v8)
    SWU(v0,v1) SWU(v3,v4) SWU(v6,v7)
    SWU(v1,v2) SWU(v4,v5) SWU(v7,v8)
    SWU(v0,v3) SWU(v5,v8) SWU(v4,v7)
    SWU(v3,v6) SWU(v1,v4) SWU(v2,v5)
    SWU(v4,v7) SWU(v4,v2) SWU(v6,v4)
    SWU(v4,v2)
    return v4;
}

// ================= kernel 1: binomial blur + quantize (R3 geometry) =========
__global__ void __launch_bounds__(256) blur_kernel(const float* __restrict__ cur,
                                                   const float* __restrict__ prev) {
    const int lane = threadIdx.x;
    const int x2   = (blockIdx.x * 32 + lane) * 2;            // W = 15*64
    const int y    = blockIdx.y * 8 + threadIdx.y;            // H = 68*8
    const int yu = max(y - 1, 0) * W;
    const int ym = y * W;
    const int yd = min(y + 1, H - 1) * W;
    const int xl = max(x2 - 1, 0);
    const int xr = min(x2 + 2, W - 1);

#pragma unroll
    for (int im = 0; im < 2; im++) {
        const float* __restrict__ img = im ? prev : cur;
        float2 u = *(const float2*)&img[yu + x2];
        float2 m = *(const float2*)&img[ym + x2];
        float2 d = *(const float2*)&img[yd + x2];
        float v0 = (u.x + 2.0f * m.x + d.x) * 0.25f;
        float v1 = (u.y + 2.0f * m.y + d.y) * 0.25f;
        float vL = __shfl_up_sync(0xffffffffu, v1, 1);
        float vR = __shfl_down_sync(0xffffffffu, v0, 1);
        if (lane == 0)
            vL = (img[yu + xl] + 2.0f * img[ym + xl] + img[yd + xl]) * 0.25f;
        if (lane == 31)
            vR = (img[yu + xr] + 2.0f * img[ym + xr] + img[yd + xr]) * 0.25f;
        float o0 = (vL + 2.0f * v0 + v1) * 0.25f;
        float o1 = (v0 + 2.0f * v1 + vR) * 0.25f;
        if (im == 0) {
            *(float2*)&g_cur_blur[ym + x2] = make_float2(o0, o1);
            *(uchar2*)&g_cur_q[ym + x2]    = make_uchar2(quant8(o0), quant8(o1));
        } else {
            *(uchar2*)&g_prev_q[ym + x2]   = make_uchar2(quant8(o0), quant8(o1));
        }
    }
    cudaTriggerProgrammaticLaunchCompletion();
}

// ========= kernel 2: match (strip smem) -> grid barrier -> flow (smem) ======
// CTA = one 64x8 strip = 8 blocks (warp per block). All flow reads hit smem.
__global__ void __launch_bounds__(256, 7) mf_kernel(float* __restrict__ out) {
    __shared__ unsigned winq[16][20];   // prev_q window strip: 16 rows x 72B (+pad)
    __shared__ unsigned tq[8][16];      // cur_q strip: 8 rows x 64B
    __shared__ float    cb[10][68];     // cur_blur halo: rows y0-1..y0+8, cols x0-1..x0+64

    const int tid  = threadIdx.x;
    const int b    = blockIdx.x;        // 0..1019
    const int sy   = b / 15, sx = b % 15;
    const int x0   = sx * 64, y0 = sy * 8;
    const int wid  = tid >> 5;
    const int lane = tid & 31;

    cudaGridDependencySynchronize();    // PDL: wait for blur

    // ---- coop load prev_q window: 16 rows x 18 words (72B/row) ----
    {
        const bool interior = (sy >= 1 && sy <= 66 && sx >= 1 && sx <= 13);
        for (int i = tid; i < 16 * 18; i += 256) {
            int wy = i / 18, ww = i - wy * 18;
            unsigned v;
            if (interior) {
                v = *(const unsigned*)(g_prev_q + (y0 - 4 + wy) * W + (x0 - 4) + ww * 4);
            } else {
                v = 0;
                int gy = clampi(y0 - 4 + wy, 0, H - 1);
#pragma unroll
                for (int c = 0; c < 4; c++) {
                    int gx = clampi(x0 - 4 + ww * 4 + c, 0, W - 1);
                    v |= (unsigned)g_prev_q[gy * W + gx] << (8 * c);
                }
            }
            winq[wy][ww] = v;
        }
    }
    // ---- coop load cur_q strip: 8 rows x 16 words (all in-image, aligned) ----
    for (int i = tid; i < 8 * 16; i += 256) {
        int ty = i >> 4, ww = i & 15;
        tq[ty][ww] = *(const unsigned*)(g_cur_q + (y0 + ty) * W + x0 + ww * 4);
    }
    // ---- coop load cur_blur halo: 10 rows x 66 floats (clamped coords) ----
    for (int i = tid; i < 10 * 66; i += 256) {
        int r = i / 66, cc = i - r * 66;
        int gy = clampi(y0 - 1 + r, 0, H - 1);
        int gx = clampi(x0 - 1 + cc, 0, W - 1);
        cb[r][cc] = g_cur_blur[gy * W + gx];
    }
    __syncthreads();

    // ================= Phase 1: SAD match (warp wid -> block sx*8+wid) =======
    {
        unsigned key = 0xffffffffu;
#pragma unroll
        for (int j = 0; j < 3; j++) {
            int c = lane + j * 32;
            if (c < NC) {
                int cy = c / 9, cx = c - cy * 9;
                int sb = wid * 8 + cx;          // start byte within 72B row
                int k8 = (sb & 3) * 8, bw = sb >> 2;
                unsigned sad = 0;
#pragma unroll
                for (int ty = 0; ty < T; ty++) {
                    const unsigned* row = &winq[ty + cy][0];
                    unsigned w0 = row[bw], w1 = row[bw + 1], w2 = row[bw + 2];
                    unsigned lo = __funnelshift_r(w0, w1, k8);
                    unsigned hi = __funnelshift_r(w1, w2, k8);
                    sad += __vsadu4(lo, tq[ty][wid * 2]) + __vsadu4(hi, tq[ty][wid * 2 + 1]);
                }
                unsigned kk = ((sad * 128u + (unsigned)c_spiral[c]) << 7) | (unsigned)c;
                key = min(key, kk);
            }
        }
#pragma unroll
        for (int s = 16; s > 0; s >>= 1)
            key = min(key, __shfl_xor_sync(0xffffffffu, key, s));

        if (lane == 0) {
            int c  = key & 127;
            int dy = c / 9 - R;
            int dx = c % 9 - R;
            g_vec[sy * WB + sx * 8 + wid] = make_char2((char)(-dy), (char)(-dx));
        }
    }

    grid_barrier(&g_barrier);

    // ================= Phase 2: median + LK subpixel (smem-resident) =========
    {
        const int bx  = sx * 8 + wid;
        const int blk = sy * WB + bx;

        // lanes 0..8 load 3x3 vec neighborhood from global (tiny, L2-hot)
        unsigned pk = 0;
        if (lane < 9) {
            int ny = clampi(sy + lane / 3 - 1, 0, HB - 1);
            int nx = clampi(bx + lane % 3 - 1, 0, WB - 1);
            char2 v = g_vec[ny * WB + nx];
            pk = (unsigned)(v.x + 4) | ((unsigned)(v.y + 4) << 8);
        }
        unsigned a0 = __shfl_sync(0xffffffffu, pk, 0);
        unsigned a1 = __shfl_sync(0xffffffffu, pk, 1);
        unsigned a2 = __shfl_sync(0xffffffffu, pk, 2);
        unsigned a3 = __shfl_sync(0xffffffffu, pk, 3);
        unsigned a4 = __shfl_sync(0xffffffffu, pk, 4);
        unsigned a5 = __shfl_sync(0xffffffffu, pk, 5);
        unsigned a6 = __shfl_sync(0xffffffffu, pk, 6);
        unsigned a7 = __shfl_sync(0xffffffffu, pk, 7);
        unsigned a8 = __shfl_sync(0xffffffffu, pk, 8);
        unsigned md = med9u(a0,a1,a2,a3,a4,a5,a6,a7,a8);
        int medy = (int)(md & 0xff) - 4;
        int medx = (int)((md >> 8) & 0xff) - 4;
        int offy = -medy, offx = -medx;

        // lane -> border pixel (28 border pixels of the 8x8 block)
        int ty, tx;
        bool act = lane < 28;
        if      (lane < 8)  { ty = 0;         tx = lane;      }
        else if (lane < 16) { ty = 7;         tx = lane - 8;  }
        else if (lane < 22) { ty = lane - 15; tx = 0;         }
        else                { ty = lane - 21; tx = 7;         }

        float a = 0.f, bb = 0.f, d = 0.f, p = 0.f, q = 0.f;
        if (act) {
            const int cl = wid * 8 + tx + 1;        // cur_blur local col (center)
            float gyv = (cb[ty + 2][cl] - cb[ty][cl]) * 0.5f;
            float gxv = (cb[ty + 1][cl + 1] - cb[ty + 1][cl - 1]) * 0.5f;
            float tmpl = (float)(((const unsigned char*)&tq[ty][0])[wid * 8 + tx]) * (1.0f / 255.0f);
            // matched pixel: window row (ty+offy+4), col (wid*8+tx+offx+4) — always in strip
            float mat = (float)(((const unsigned char*)&winq[ty + offy + 4][0])[wid * 8 + tx + offx + 4]) * (1.0f / 255.0f);
            float diff = mat - tmpl;
            a  = gxv * gxv;
            bb = gxv * gyv;
            d  = gyv * gyv;
            p  = diff * gxv;
            q  = diff * gyv;
        }
#pragma unroll
        for (int s = 16; s > 0; s >>= 1) {
            a  += __shfl_xor_sync(0xffffffffu, a,  s);
            bb += __shfl_xor_sync(0xffffffffu, bb, s);
            d  += __shfl_xor_sync(0xffffffffu, d,  s);
            p  += __shfl_xor_sync(0xffffffffu, p,  s);
            q  += __shfl_xor_sync(0xffffffffu, q,  s);
        }
        if (lane == 0) {
            float det = a * d - bb * bb;
            bool  bad = (det <= 1e-6f);
            float sd  = bad ? 1.0f : det;
            float su  = (d * p - bb * q) / sd;
            float sv  = (a * q - bb * p) / sd;
            float subv = (bad || fabsf(sv) >= 1.0f) ? 0.0f : sv;
            float subu = (bad || fabsf(su) >= 1.0f) ? 0.0f : su;
            out[blk]      = (float)medy + subv;
            out[NB + blk] = (float)medx + subu;
        }
    }
}

// ---------------- entry point ------------------------------------------------
extern "C" void kernel_launch(void* const* d_in, const int* in_sizes, int n_in,
                              void* d_out, int out_size) {
    const float* cur  = (const float*)d_in[0];
    const float* prev = (const float*)d_in[1];
    float* out = (float*)d_out;

    {
        dim3 bt(32, 8);
        dim3 bg(W / 64, H / 8);          // 15 x 68
        blur_kernel<<<bg, bt>>>(cur, prev);
    }

    cudaLaunchAttribute attr[1];
    attr[0].id = cudaLaunchAttributeProgrammaticStreamSerialization;
    attr[0].val.programmaticStreamSerializationAllowed = 1;
    {
        cudaLaunchConfig_t cfg = {};
        cfg.gridDim  = dim3(GRID, 1, 1);
        cfg.blockDim = dim3(256, 1, 1);
        cfg.dynamicSmemBytes = 0;
        cfg.stream = 0;
        cfg.attrs = attr;
        cfg.numAttrs = 1;
        cudaLaunchKernelEx(&cfg, mf_kernel, out);
    }
}

// round 9
// speedup vs baseline: 1.3130x; 1.3029x over previous
#include <cuda_runtime.h>

// Problem constants (fixed by setup_inputs: img [1,1,544,960], T=8, R=4)
#define H  544
#define W  960
#define T  8
#define R  4
#define HB (H/T)                  // 68
#define WB (W/T)                  // 120
#define NB (HB*WB)                // 8160
#define NC ((2*R+1)*(2*R+1))      // 81

// ---------------- scratch (device globals) ----------------------------------
__device__ float         g_cur_blur[H*W];
__device__ unsigned char g_cur_q[H*W];
__device__ unsigned char g_prev_q[H*W];
__device__ char2         g_vec[NB];          // (vy, vx) = (-dy, -dx)

// spiral rank LUT (row-major over (dy+R, dx+R)), precomputed for R=4
__constant__ unsigned char c_spiral[NC] = {
    74, 73, 72, 71, 70, 69, 68, 67, 66,
    75, 44, 43, 42, 41, 40, 39, 38, 65,
    76, 45, 22, 21, 20, 19, 18, 37, 64,
    77, 46, 23,  8,  7,  6, 17, 36, 63,
    78, 47, 24,  9,  1,  5, 16, 35, 62,
    79, 48, 25,  2,  3,  4, 15, 34, 61,
    80, 49, 10, 11, 12, 13, 14, 33, 60,
    81, 26, 27, 28, 29, 30, 31, 32, 59,
    50, 51, 52, 53, 54, 55, 56, 57, 58
};

__device__ __forceinline__ unsigned char quant8(float v) {
    return (unsigned char)fminf(fmaxf(rintf(v * 255.0f), 0.0f), 255.0f);
}
__device__ __forceinline__ int clampi(int v, int lo, int hi) {
    return min(max(v, lo), hi);
}

// ================= kernel 1: binomial blur + quantize ========================
// R3 geometry (warp = 64px row, 2px/lane) with ALL loads hoisted (MLP 12+).
__global__ void __launch_bounds__(256) blur_kernel(const float* __restrict__ cur,
                                                   const float* __restrict__ prev) {
    const int lane = threadIdx.x;
    const int x2   = (blockIdx.x * 32 + lane) * 2;            // W = 15*64
    const int y    = blockIdx.y * 8 + threadIdx.y;            // H = 68*8
    const int yu = max(y - 1, 0) * W;
    const int ym = y * W;
    const int yd = min(y + 1, H - 1) * W;
    const bool eL = (lane == 0), eR = (lane == 31);
    const int xe = eL ? max(x2 - 1, 0) : min(x2 + 2, W - 1);  // only edge lanes use it

    // ---- issue every global load up front (12 vector + up to 6 scalar) ----
    float2 u0 = *(const float2*)&cur [yu + x2];
    float2 m0 = *(const float2*)&cur [ym + x2];
    float2 d0 = *(const float2*)&cur [yd + x2];
    float2 u1 = *(const float2*)&prev[yu + x2];
    float2 m1 = *(const float2*)&prev[ym + x2];
    float2 d1 = *(const float2*)&prev[yd + x2];
    float eu0 = 0.f, em0 = 0.f, ed0 = 0.f, eu1 = 0.f, em1 = 0.f, ed1 = 0.f;
    if (eL || eR) {
        eu0 = cur [yu + xe]; em0 = cur [ym + xe]; ed0 = cur [yd + xe];
        eu1 = prev[yu + xe]; em1 = prev[ym + xe]; ed1 = prev[yd + xe];
    }

    // ---- cur ----
    {
        float v0 = (u0.x + 2.0f * m0.x + d0.x) * 0.25f;
        float v1 = (u0.y + 2.0f * m0.y + d0.y) * 0.25f;
        float ve = (eu0 + 2.0f * em0 + ed0) * 0.25f;
        float vL = __shfl_up_sync(0xffffffffu, v1, 1);
        float vR = __shfl_down_sync(0xffffffffu, v0, 1);
        if (eL) vL = ve;
        if (eR) vR = ve;
        float o0 = (vL + 2.0f * v0 + v1) * 0.25f;
        float o1 = (v0 + 2.0f * v1 + vR) * 0.25f;
        *(float2*)&g_cur_blur[ym + x2] = make_float2(o0, o1);
        *(uchar2*)&g_cur_q[ym + x2]    = make_uchar2(quant8(o0), quant8(o1));
    }
    // ---- prev ----
    {
        float v0 = (u1.x + 2.0f * m1.x + d1.x) * 0.25f;
        float v1 = (u1.y + 2.0f * m1.y + d1.y) * 0.25f;
        float ve = (eu1 + 2.0f * em1 + ed1) * 0.25f;
        float vL = __shfl_up_sync(0xffffffffu, v1, 1);
        float vR = __shfl_down_sync(0xffffffffu, v0, 1);
        if (eL) vL = ve;
        if (eR) vR = ve;
        float o0 = (vL + 2.0f * v0 + v1) * 0.25f;
        float o1 = (v0 + 2.0f * v1 + vR) * 0.25f;
        *(uchar2*)&g_prev_q[ym + x2]   = make_uchar2(quant8(o0), quant8(o1));
    }
    cudaTriggerProgrammaticLaunchCompletion();
}

// ================= kernel 2: SAD match, strip-coalesced smem =================
// CTA = one 64x8 strip = 8 template blocks (warp per block).
__global__ void __launch_bounds__(256) match_kernel() {
    __shared__ unsigned winq[16][20];   // prev_q window strip: 16 rows x 72B (+pad)
    __shared__ unsigned tq[8][16];      // cur_q strip: 8 rows x 64B

    const int tid  = threadIdx.x;
    const int b    = blockIdx.x;        // 0..1019
    const int sy   = b / 15, sx = b % 15;
    const int x0   = sx * 64, y0 = sy * 8;
    const int wid  = tid >> 5;
    const int lane = tid & 31;

    cudaGridDependencySynchronize();    // PDL: wait for blur

    // ---- coop load prev_q window: 16 rows x 18 words (72B/row) ----
    {
        const bool interior = (sy >= 1 && sy <= 66 && sx >= 1 && sx <= 13);
        for (int i = tid; i < 16 * 18; i += 256) {
            int wy = i / 18, ww = i - wy * 18;
            unsigned v;
            if (interior) {
                v = *(const unsigned*)(g_prev_q + (y0 - 4 + wy) * W + (x0 - 4) + ww * 4);
            } else {
                v = 0;
                int gy = clampi(y0 - 4 + wy, 0, H - 1);
#pragma unroll
                for (int c = 0; c < 4; c++) {
                    int gx = clampi(x0 - 4 + ww * 4 + c, 0, W - 1);
                    v |= (unsigned)g_prev_q[gy * W + gx] << (8 * c);
                }
            }
            winq[wy][ww] = v;
        }
    }
    // ---- coop load cur_q strip: 8 rows x 16 words (all in-image, aligned) ----
    for (int i = tid; i < 8 * 16; i += 256) {
        int ty = i >> 4, ww = i & 15;
        tq[ty][ww] = *(const unsigned*)(g_cur_q + (y0 + ty) * W + x0 + ww * 4);
    }
    __syncthreads();

    // ---- 81 candidates over 32 lanes (warp wid -> block sx*8+wid) ----
    unsigned key = 0xffffffffu;
#pragma unroll
    for (int j = 0; j < 3; j++) {
        int c = lane + j * 32;
        if (c < NC) {
            int cy = c / 9, cx = c - cy * 9;
            int sb = wid * 8 + cx;          // start byte within 72B row
            int k8 = (sb & 3) * 8, bw = sb >> 2;
            unsigned sad = 0;
#pragma unroll
            for (int ty = 0; ty < T; ty++) {
                const unsigned* row = &winq[ty + cy][0];
                unsigned w0 = row[bw], w1 = row[bw + 1], w2 = row[bw + 2];
                unsigned lo = __funnelshift_r(w0, w1, k8);
                unsigned hi = __funnelshift_r(w1, w2, k8);
                sad += __vsadu4(lo, tq[ty][wid * 2]) + __vsadu4(hi, tq[ty][wid * 2 + 1]);
            }
            unsigned kk = ((sad * 128u + (unsigned)c_spiral[c]) << 7) | (unsigned)c;
            key = min(key, kk);
        }
    }
#pragma unroll
    for (int s = 16; s > 0; s >>= 1)
        key = min(key, __shfl_xor_sync(0xffffffffu, key, s));

    if (lane == 0) {
        int c  = key & 127;
        int dy = c / 9 - R;
        int dx = c % 9 - R;
        g_vec[sy * WB + sx * 8 + wid] = make_char2((char)(-dy), (char)(-dx));
    }
    cudaTriggerProgrammaticLaunchCompletion();
}

// ---------------- packed byte-SIMD median of 9 (Paeth network) --------------
#define SWU(a,b) { unsigned _t = __vminu4(a,b); b = __vmaxu4(a,b); a = _t; }
__device__ __forceinline__ unsigned med9u(unsigned v0, unsigned v1, unsigned v2,
                                          unsigned v3, unsigned v4, unsigned v5,
                                          unsigned v6, unsigned v7, unsigned v8) {
    SWU(v1,v2) SWU(v4,v5) SWU(v7,v8)
    SWU(v0,v1) SWU(v3,v4) SWU(v6,v7)
    SWU(v1,v2) SWU(v4,v5) SWU(v7,v8)
    SWU(v0,v3) SWU(v5,v8) SWU(v4,v7)
    SWU(v3,v6) SWU(v1,v4) SWU(v2,v5)
    SWU(v4,v7) SWU(v4,v2) SWU(v6,v4)
    SWU(v4,v2)
    return v4;
}

// ================= kernel 3: median + LK subpixel + flow output ==============
__global__ void __launch_bounds__(256) flow_kernel(float* __restrict__ out) {
    const int wid  = threadIdx.x >> 5;
    const int lane = threadIdx.x & 31;
    const int blk  = blockIdx.x * 8 + wid;       // NB = 1020*8 exactly
    const int by = blk / WB, bx = blk % WB;

    // lane -> border pixel (28 border pixels of the 8x8 block)
    int ty, tx;
    bool act = lane < 28;
    if      (lane < 8)  { ty = 0;         tx = lane;      }
    else if (lane < 16) { ty = 7;         tx = lane - 8;  }
    else if (lane < 22) { ty = lane - 15; tx = 0;         }
    else                { ty = lane - 21; tx = 7;         }
    const int gy0 = by * T + ty, gx0 = bx * T + tx;

    cudaGridDependencySynchronize();             // wait for match results

    // lanes 0..8 load the 3x3 neighborhood; pack (vy+4) | (vx+4)<<8
    unsigned pk = 0;
    if (lane < 9) {
        int ny = clampi(by + lane / 3 - 1, 0, HB - 1);
        int nx = clampi(bx + lane % 3 - 1, 0, WB - 1);
        char2 v = g_vec[ny * WB + nx];
        pk = (unsigned)(v.x + 4) | ((unsigned)(v.y + 4) << 8);
    }
    unsigned a0 = __shfl_sync(0xffffffffu, pk, 0);
    unsigned a1 = __shfl_sync(0xffffffffu, pk, 1);
    unsigned a2 = __shfl_sync(0xffffffffu, pk, 2);
    unsigned a3 = __shfl_sync(0xffffffffu, pk, 3);
    unsigned a4 = __shfl_sync(0xffffffffu, pk, 4);
    unsigned a5 = __shfl_sync(0xffffffffu, pk, 5);
    unsigned a6 = __shfl_sync(0xffffffffu, pk, 6);
    unsigned a7 = __shfl_sync(0xffffffffu, pk, 7);
    unsigned a8 = __shfl_sync(0xffffffffu, pk, 8);
    unsigned md = med9u(a0,a1,a2,a3,a4,a5,a6,a7,a8);
    int medy = (int)(md & 0xff) - 4;
    int medx = (int)((md >> 8) & 0xff) - 4;
    int offy = -medy, offx = -medx;

    float a = 0.f, b = 0.f, d = 0.f, p = 0.f, q = 0.f;
    if (act) {
        float gyv = (g_cur_blur[min(gy0 + 1, H - 1) * W + gx0] -
                     g_cur_blur[max(gy0 - 1, 0)     * W + gx0]) * 0.5f;
        float gxv = (g_cur_blur[gy0 * W + min(gx0 + 1, W - 1)] -
                     g_cur_blur[gy0 * W + max(gx0 - 1, 0)]) * 0.5f;
        float tmpl = (float)g_cur_q[gy0 * W + gx0] * (1.0f / 255.0f);
        int my = clampi(gy0 + offy, 0, H - 1);
        int mx = clampi(gx0 + offx, 0, W - 1);
        float mat  = (float)g_prev_q[my * W + mx] * (1.0f / 255.0f);
        float diff = mat - tmpl;
        a = gxv * gxv;
        b = gxv * gyv;
        d = gyv * gyv;
        p = diff * gxv;
        q = diff * gyv;
    }
#pragma unroll
    for (int s = 16; s > 0; s >>= 1) {
        a += __shfl_xor_sync(0xffffffffu, a, s);
        b += __shfl_xor_sync(0xffffffffu, b, s);
        d += __shfl_xor_sync(0xffffffffu, d, s);
        p += __shfl_xor_sync(0xffffffffu, p, s);
        q += __shfl_xor_sync(0xffffffffu, q, s);
    }
    if (lane == 0) {
        float det = a * d - b * b;
        bool  bad = (det <= 1e-6f);
        float sd  = bad ? 1.0f : det;
        float su  = (d * p - b * q) / sd;
        float sv  = (a * q - b * p) / sd;
        float subv = (bad || fabsf(sv) >= 1.0f) ? 0.0f : sv;
        float subu = (bad || fabsf(su) >= 1.0f) ? 0.0f : su;
        out[blk]      = (float)medy + subv;
        out[NB + blk] = (float)medx + subu;
    }
}

// ---------------- entry point ------------------------------------------------
extern "C" void kernel_launch(void* const* d_in, const int* in_sizes, int n_in,
                              void* d_out, int out_size) {
    const float* cur  = (const float*)d_in[0];
    const float* prev = (const float*)d_in[1];
    float* out = (float*)d_out;

    {
        dim3 bt(32, 8);
        dim3 bg(W / 64, H / 8);          // 15 x 68
        blur_kernel<<<bg, bt>>>(cur, prev);
    }

    cudaLaunchAttribute attr[1];
    attr[0].id = cudaLaunchAttributeProgrammaticStreamSerialization;
    attr[0].val.programmaticStreamSerializationAllowed = 1;
    {
        cudaLaunchConfig_t cfg = {};
        cfg.gridDim  = dim3(1020, 1, 1);
        cfg.blockDim = dim3(256, 1, 1);
        cfg.dynamicSmemBytes = 0;
        cfg.stream = 0;
        cfg.attrs = attr;
        cfg.numAttrs = 1;
        cudaLaunchKernelEx(&cfg, match_kernel);
    }
    {
        cudaLaunchConfig_t cfg = {};
        cfg.gridDim  = dim3(NB / 8, 1, 1);
        cfg.blockDim = dim3(256, 1, 1);
        cfg.dynamicSmemBytes = 0;
        cfg.stream = 0;
        cfg.attrs = attr;
        cfg.numAttrs = 1;
        cudaLaunchKernelEx(&cfg, flow_kernel, out);
    }
}